// round 1
// baseline (speedup 1.0000x reference)
#include <cuda_runtime.h>
#include <cuda_bf16.h>
#include <cstdint>

#define KDIM 256
#define TILE 32
#define NWARP 8
#define NIT 50

__device__ float g_loss[512];

static constexpr int SMEM_MS_OFF   = 0;
static constexpr int SMEM_TILE_OFF = KDIM * KDIM * 2;                       // 131072
static constexpr int SMEM_FSH_OFF  = SMEM_TILE_OFF + KDIM * (TILE + 1) * 4; // +33792
static constexpr int SMEM_GSH_OFF  = SMEM_FSH_OFF + KDIM * 4;
static constexpr int SMEM_RED_OFF  = SMEM_GSH_OFF + KDIM * 4;
static constexpr int SMEM_BYTES    = SMEM_RED_OFF + 64 * 4;                 // 167168

__global__ void __launch_bounds__(256)
cacis_main(const float* __restrict__ scores, const int* __restrict__ targets,
           const float* __restrict__ C)
{
    extern __shared__ unsigned char smem[];
    __nv_bfloat16* MS  = reinterpret_cast<__nv_bfloat16*>(smem + SMEM_MS_OFF);
    float*         tile = reinterpret_cast<float*>(smem + SMEM_TILE_OFF);
    float*         fsh  = reinterpret_cast<float*>(smem + SMEM_FSH_OFF);
    float*         gsh  = reinterpret_cast<float*>(smem + SMEM_GSH_OFF);
    float*         red  = reinterpret_cast<float*>(smem + SMEM_RED_OFF);

    const int t    = threadIdx.x;
    const int lane = t & 31;
    const int warp = t >> 5;
    const int b    = blockIdx.x;
    const float* __restrict__ Cb = C + (size_t)b * (KDIM * KDIM);

    fsh[t] = 0.5f * scores[b * KDIM + t];
    __syncthreads();
    const float f_r = fsh[t];

    // ---------------- PASS 1: sum(C), trace(C), min(f_i+f_j+C_ij) ----------------
    float psum = 0.f, ptrc = 0.f, pmin = 3.402823466e38f;
    for (int j0 = 0; j0 < KDIM; j0 += TILE) {
#pragma unroll
        for (int kk = 0; kk < TILE; kk++) {
            int lin = (kk << 8) + t;
            int r = lin >> 5, c = lin & 31;
            tile[r * (TILE + 1) + c] = Cb[(r << 8) + j0 + c];
        }
        __syncthreads();
#pragma unroll
        for (int c = 0; c < TILE; c++) {
            float v = tile[t * (TILE + 1) + c];
            psum += v;
            if ((j0 + c) == t) ptrc += v;
            pmin = fminf(pmin, f_r + fsh[j0 + c] + v);
        }
        __syncthreads();
    }
#pragma unroll
    for (int o = 16; o; o >>= 1) {
        psum += __shfl_xor_sync(0xffffffffu, psum, o);
        ptrc += __shfl_xor_sync(0xffffffffu, ptrc, o);
        pmin  = fminf(pmin, __shfl_xor_sync(0xffffffffu, pmin, o));
    }
    if (lane == 0) { red[warp] = psum; red[8 + warp] = ptrc; red[16 + warp] = pmin; }
    __syncthreads();
    if (t == 0) {
        float s = 0.f, tr = 0.f, mn = 3.402823466e38f;
#pragma unroll
        for (int w = 0; w < NWARP; w++) { s += red[w]; tr += red[8 + w]; mn = fminf(mn, red[16 + w]); }
        float eps = fmaxf((s - tr) * (1.0f / (KDIM * KDIM - KDIM)), 1e-8f);
        red[24] = eps; red[25] = 1.0f / eps; red[26] = mn;
    }
    __syncthreads();
    const float eps = red[24], inv_eps = red[25], minval = red[26];

    // ---------------- PASS 2: M (bf16 col-major in smem) + rowsums ----------------
    float rowsum = 0.f;
    for (int j0 = 0; j0 < KDIM; j0 += TILE) {
#pragma unroll
        for (int kk = 0; kk < TILE; kk++) {
            int lin = (kk << 8) + t;
            int r = lin >> 5, c = lin & 31;
            tile[r * (TILE + 1) + c] = Cb[(r << 8) + j0 + c];
        }
        __syncthreads();
#pragma unroll
        for (int c = 0; c < TILE; c++) {
            float v = tile[t * (TILE + 1) + c];
            float m = __expf((minval - (f_r + fsh[j0 + c] + v)) * inv_eps);
            rowsum += m;
            MS[((j0 + c) << 8) + t] = __float2bfloat16(m);   // MS[col*256 + row]
        }
        __syncthreads();
    }
    gsh[t] = rowsum * (2.0f / KDIM);   // grad_0
    __syncthreads();

    if (warp != 0) return;   // all FW state lives in warp 0 — no more block barriers

    // ---------------- Frank-Wolfe: 50 iters, warp-local ----------------
    float g[8], a[8];
#pragma unroll
    for (int k = 0; k < 8; k++) { g[k] = gsh[lane * 8 + k]; a[k] = 1.0f / KDIM; }

    for (int it = 0; it < NIT; it++) {
        // argmin with first-index tie-break: key = (bits(grad)<<32)|idx, grad>0
        unsigned long long best = 0xFFFFFFFFFFFFFFFFull;
#pragma unroll
        for (int k = 0; k < 8; k++) {
            unsigned long long cand =
                ((unsigned long long)__float_as_uint(g[k]) << 32) | (unsigned)(lane * 8 + k);
            best = (cand < best) ? cand : best;
        }
#pragma unroll
        for (int o = 16; o; o >>= 1) {
            unsigned long long other = __shfl_xor_sync(0xffffffffu, best, o);
            best = (other < best) ? other : best;
        }
        int istar = (int)(best & 0xFFu);

        float gamma = 2.0f / ((float)it + 2.0f);
        float om = 1.0f - gamma;
        float tg = 2.0f * gamma;

        // column M[:, istar]: 8 consecutive bf16 per lane = one LDS.128
        uint4 q = *reinterpret_cast<const uint4*>(MS + (istar << 8) + lane * 8);
        __nv_bfloat162* h2 = reinterpret_cast<__nv_bfloat162*>(&q);
        float mcol[8];
#pragma unroll
        for (int p = 0; p < 4; p++) {
            float2 f2 = __bfloat1622float2(h2[p]);
            mcol[2 * p] = f2.x; mcol[2 * p + 1] = f2.y;
        }
#pragma unroll
        for (int k = 0; k < 8; k++) {
            a[k] = om * a[k] + (((lane * 8 + k) == istar) ? gamma : 0.f);
            g[k] = fmaf(tg, mcol[k], om * g[k]);
        }
    }

    // ---------------- exact val = alpha^T M alpha over the <=50-point support ----------------
    int*   sidx = reinterpret_cast<int*>(tile);
    float* sval = tile + 64;
    int nS = 0;
#pragma unroll
    for (int k = 0; k < 8; k++) {
        bool nz = (a[k] > 0.f);
        unsigned m = __ballot_sync(0xffffffffu, nz);
        if (nz) {
            int pos = nS + __popc(m & ((1u << lane) - 1u));
            sidx[pos] = lane * 8 + k;
            sval[pos] = a[k];
        }
        nS += __popc(m);
    }
    __syncwarp();

    float vp = 0.f;
    int tot = nS * nS;
    for (int p = lane; p < tot; p += 32) {
        int pi = p / nS, pj = p - pi * nS;
        int i = sidx[pi], j = sidx[pj];
        float e = fsh[i] + fsh[j] + Cb[(i << 8) + j];     // L2-resident
        vp += sval[pi] * sval[pj] * __expf((minval - e) * inv_eps);
    }
#pragma unroll
    for (int o = 16; o; o >>= 1) vp += __shfl_xor_sync(0xffffffffu, vp, o);

    if (lane == 0) {
        // conjugate = -eps*(logval + shift) = minval - eps*log(val)
        g_loss[b] = minval - eps * logf(vp) - scores[b * KDIM + targets[b]];
    }
}

__global__ void reduce_kernel(float* __restrict__ out, int B)
{
    __shared__ float sh[32];
    int t = threadIdx.x;
    float v = (t < B) ? g_loss[t] : 0.f;
#pragma unroll
    for (int o = 16; o; o >>= 1) v += __shfl_xor_sync(0xffffffffu, v, o);
    int lane = t & 31, warp = t >> 5;
    if (lane == 0) sh[warp] = v;
    __syncthreads();
    if (warp == 0) {
        int nw = (blockDim.x + 31) >> 5;
        float x = (lane < nw) ? sh[lane] : 0.f;
#pragma unroll
        for (int o = 16; o; o >>= 1) x += __shfl_xor_sync(0xffffffffu, x, o);
        if (t == 0) out[0] = x / (float)B;
    }
}

extern "C" void kernel_launch(void* const* d_in, const int* in_sizes, int n_in,
                              void* d_out, int out_size)
{
    // identify inputs by size: targets (smallest), C (largest), scores (middle)
    int imin = 0, imax = 0;
    for (int i = 1; i < n_in; i++) {
        if (in_sizes[i] < in_sizes[imin]) imin = i;
        if (in_sizes[i] > in_sizes[imax]) imax = i;
    }
    int imid = 3 - imin - imax;
    const float* scores  = (const float*)d_in[imid];
    const int*   targets = (const int*)d_in[imin];
    const float* C       = (const float*)d_in[imax];
    int B = in_sizes[imin];

    cudaFuncSetAttribute(cacis_main, cudaFuncAttributeMaxDynamicSharedMemorySize, SMEM_BYTES);
    cacis_main<<<B, 256, SMEM_BYTES>>>(scores, targets, C);
    reduce_kernel<<<1, 512>>>((float*)d_out, B);
}

// round 2
// speedup vs baseline: 1.7833x; 1.7833x over previous
#include <cuda_runtime.h>
#include <cuda_bf16.h>
#include <cstdint>

#define KDIM 256
#define NIT 50
#define TPITCH 36   // floats per tile row: 144B = 16 mod 128 -> conflict-free LDS.128/STS.128

__device__ float g_loss[512];
__device__ unsigned g_cnt = 0;

static constexpr int SMEM_MS_OFF   = 0;                         // 256*256 bf16 = 131072 B
static constexpr int SMEM_TILE_OFF = 131072;                    // 256*36 floats = 36864 B
static constexpr int SMEM_FSH_OFF  = SMEM_TILE_OFF + 36864;     // 167936
static constexpr int SMEM_GSH_OFF  = SMEM_FSH_OFF + 1024;       // 168960
static constexpr int SMEM_RED_OFF  = SMEM_GSH_OFF + 1024;       // 169984
static constexpr int SMEM_BYTES    = SMEM_RED_OFF + 128;        // 170112

__global__ void __launch_bounds__(256)
cacis_main(const float* __restrict__ scores, const int* __restrict__ targets,
           const float* __restrict__ C, float* __restrict__ out, int B)
{
    extern __shared__ unsigned char smem[];
    __nv_bfloat16* MS   = reinterpret_cast<__nv_bfloat16*>(smem + SMEM_MS_OFF);
    float*         tile = reinterpret_cast<float*>(smem + SMEM_TILE_OFF);
    float*         fsh  = reinterpret_cast<float*>(smem + SMEM_FSH_OFF);
    float*         gsh  = reinterpret_cast<float*>(smem + SMEM_GSH_OFF);
    float*         red  = reinterpret_cast<float*>(smem + SMEM_RED_OFF);
    const float4*  fsh4 = reinterpret_cast<const float4*>(fsh);

    const int t    = threadIdx.x;
    const int lane = t & 31;
    const int warp = t >> 5;
    const int b    = blockIdx.x;
    const float* __restrict__ Cb  = C + (size_t)b * (KDIM * KDIM);
    const float4* __restrict__ Cb4 = reinterpret_cast<const float4*>(Cb);

    fsh[t] = 0.5f * scores[b * KDIM + t];
    __syncthreads();
    const float f_r = fsh[t];

    // ---------------- PASS 1: sum(C), trace(C), min(f_i+f_j+C) — streamed, no smem ----------------
    {
        float4 fc4 = fsh4[t & 63];
        const int colbase = (t & 63) * 4;
        float psum = 0.f, ptrc = 0.f, pmin = 3.402823466e38f;
#pragma unroll 4
        for (int k = 0; k < 64; k++) {
            int row = 4 * k + (t >> 6);
            float fr = fsh[row];
            float4 v = Cb4[k * 256 + t];
            psum += (v.x + v.y) + (v.z + v.w);
            pmin = fminf(pmin, fr + fminf(fminf(fc4.x + v.x, fc4.y + v.y),
                                          fminf(fc4.z + v.z, fc4.w + v.w)));
            if (colbase + 0 == row) ptrc += v.x;
            if (colbase + 1 == row) ptrc += v.y;
            if (colbase + 2 == row) ptrc += v.z;
            if (colbase + 3 == row) ptrc += v.w;
        }
#pragma unroll
        for (int o = 16; o; o >>= 1) {
            psum += __shfl_xor_sync(0xffffffffu, psum, o);
            ptrc += __shfl_xor_sync(0xffffffffu, ptrc, o);
            pmin  = fminf(pmin, __shfl_xor_sync(0xffffffffu, pmin, o));
        }
        if (lane == 0) { red[warp] = psum; red[8 + warp] = ptrc; red[16 + warp] = pmin; }
    }
    __syncthreads();
    if (t == 0) {
        float s = 0.f, tr = 0.f, mn = 3.402823466e38f;
#pragma unroll
        for (int w = 0; w < 8; w++) { s += red[w]; tr += red[8 + w]; mn = fminf(mn, red[16 + w]); }
        float eps = fmaxf((s - tr) * (1.0f / (KDIM * KDIM - KDIM)), 1e-8f);
        red[24] = eps; red[25] = 1.0f / eps; red[26] = mn;
    }
    __syncthreads();
    const float eps = red[24], inv_eps = red[25], minval = red[26];

    // ---------------- PASS 2: M = exp(..) -> bf16 col-major + rowsums (vectorized tiles) ----------------
    float rowsum = 0.f;
    for (int j0 = 0; j0 < KDIM; j0 += 32) {
#pragma unroll
        for (int kk = 0; kk < 8; kk++) {
            int f4  = kk * 256 + t;
            int row = f4 >> 3;
            int c4  = f4 & 7;
            float4 v = Cb4[row * 64 + (j0 >> 2) + c4];
            *reinterpret_cast<float4*>(tile + row * TPITCH + c4 * 4) = v;
        }
        __syncthreads();
#pragma unroll
        for (int c4 = 0; c4 < 8; c4++) {
            float4 v  = *reinterpret_cast<const float4*>(tile + t * TPITCH + c4 * 4);
            float4 fc = fsh4[(j0 >> 2) + c4];
            float base = minval - f_r;
            float m0 = __expf((base - (fc.x + v.x)) * inv_eps);
            float m1 = __expf((base - (fc.y + v.y)) * inv_eps);
            float m2 = __expf((base - (fc.z + v.z)) * inv_eps);
            float m3 = __expf((base - (fc.w + v.w)) * inv_eps);
            int col = j0 + c4 * 4;
            MS[(col + 0) * 256 + t] = __float2bfloat16(m0);
            MS[(col + 1) * 256 + t] = __float2bfloat16(m1);
            MS[(col + 2) * 256 + t] = __float2bfloat16(m2);
            MS[(col + 3) * 256 + t] = __float2bfloat16(m3);
            rowsum += (m0 + m1) + (m2 + m3);
        }
        __syncthreads();
    }
    gsh[t] = rowsum * (2.0f / KDIM);   // grad_0
    __syncthreads();

    if (warp != 0) return;   // FW + epilogue live entirely in warp 0

    // ---------------- Frank-Wolfe: 50 iters, REDUX argmin ----------------
    float g[8], a[8];
#pragma unroll
    for (int k = 0; k < 8; k++) { g[k] = gsh[lane * 8 + k]; a[k] = 1.0f / KDIM; }

    for (int it = 0; it < NIT; it++) {
        // key = (gradbits & ~0xFF) | idx  (grad > 0 so positive-float bit order holds)
        unsigned c0 = (__float_as_uint(g[0]) & 0xFFFFFF00u) | (unsigned)(lane * 8 + 0);
        unsigned c1 = (__float_as_uint(g[1]) & 0xFFFFFF00u) | (unsigned)(lane * 8 + 1);
        unsigned c2 = (__float_as_uint(g[2]) & 0xFFFFFF00u) | (unsigned)(lane * 8 + 2);
        unsigned c3 = (__float_as_uint(g[3]) & 0xFFFFFF00u) | (unsigned)(lane * 8 + 3);
        unsigned c4 = (__float_as_uint(g[4]) & 0xFFFFFF00u) | (unsigned)(lane * 8 + 4);
        unsigned c5 = (__float_as_uint(g[5]) & 0xFFFFFF00u) | (unsigned)(lane * 8 + 5);
        unsigned c6 = (__float_as_uint(g[6]) & 0xFFFFFF00u) | (unsigned)(lane * 8 + 6);
        unsigned c7 = (__float_as_uint(g[7]) & 0xFFFFFF00u) | (unsigned)(lane * 8 + 7);
        unsigned m01 = min(c0, c1), m23 = min(c2, c3), m45 = min(c4, c5), m67 = min(c6, c7);
        unsigned key = min(min(m01, m23), min(m45, m67));
        key = __reduce_min_sync(0xffffffffu, key);
        int istar = (int)(key & 0xFFu);

        float gamma = 2.0f / ((float)it + 2.0f);
        float om = 1.0f - gamma;
        float tg = 2.0f * gamma;

        uint4 q = *reinterpret_cast<const uint4*>(MS + (istar << 8) + lane * 8);
        __nv_bfloat162* h2 = reinterpret_cast<__nv_bfloat162*>(&q);
        float mcol[8];
#pragma unroll
        for (int p = 0; p < 4; p++) {
            float2 f2 = __bfloat1622float2(h2[p]);
            mcol[2 * p] = f2.x; mcol[2 * p + 1] = f2.y;
        }
#pragma unroll
        for (int k = 0; k < 8; k++) {
            a[k] = om * a[k] + (((lane * 8 + k) == istar) ? gamma : 0.f);
            g[k] = fmaf(tg, mcol[k], om * g[k]);
        }
    }

    // ---------------- exact val = alpha^T M alpha over the <=50-point support ----------------
    int*   sidx = reinterpret_cast<int*>(tile);
    float* sval = tile + 64;
    int nS = 0;
#pragma unroll
    for (int k = 0; k < 8; k++) {
        bool nz = (a[k] > 0.f);
        unsigned m = __ballot_sync(0xffffffffu, nz);
        if (nz) {
            int pos = nS + __popc(m & ((1u << lane) - 1u));
            sidx[pos] = lane * 8 + k;
            sval[pos] = a[k];
        }
        nS += __popc(m);
    }
    __syncwarp();

    float vp = 0.f;
    for (int pi = 0; pi < nS; pi++) {
        int i = sidx[pi];
        float base = sval[pi];
        float fi = minval - fsh[i];
        const float* Crow = Cb + (i << 8);
        for (int pj = lane; pj < nS; pj += 32) {
            int j = sidx[pj];
            float e = (fi - fsh[j] - Crow[j]) * inv_eps;
            vp += base * sval[pj] * __expf(e);
        }
    }
#pragma unroll
    for (int o = 16; o; o >>= 1) vp += __shfl_xor_sync(0xffffffffu, vp, o);

    // ---------------- per-batch loss + fused last-CTA mean reduction ----------------
    unsigned prev = 0;
    if (lane == 0) {
        g_loss[b] = minval - eps * logf(vp) - scores[b * KDIM + targets[b]];
        __threadfence();
        prev = atomicAdd(&g_cnt, 1u);
    }
    prev = __shfl_sync(0xffffffffu, prev, 0);
    if ((int)prev == B - 1) {
        __threadfence();
        float s = 0.f;
        volatile float* gl = g_loss;
        for (int i = lane; i < B; i += 32) s += gl[i];
#pragma unroll
        for (int o = 16; o; o >>= 1) s += __shfl_xor_sync(0xffffffffu, s, o);
        if (lane == 0) { out[0] = s / (float)B; g_cnt = 0; }
    }
}

extern "C" void kernel_launch(void* const* d_in, const int* in_sizes, int n_in,
                              void* d_out, int out_size)
{
    int imin = 0, imax = 0;
    for (int i = 1; i < n_in; i++) {
        if (in_sizes[i] < in_sizes[imin]) imin = i;
        if (in_sizes[i] > in_sizes[imax]) imax = i;
    }
    int imid = 3 - imin - imax;
    const float* scores  = (const float*)d_in[imid];
    const int*   targets = (const int*)d_in[imin];
    const float* C       = (const float*)d_in[imax];
    int B = in_sizes[imin];

    cudaFuncSetAttribute(cacis_main, cudaFuncAttributeMaxDynamicSharedMemorySize, SMEM_BYTES);
    cacis_main<<<B, 256, SMEM_BYTES>>>(scores, targets, C, (float*)d_out, B);
}

// round 3
// speedup vs baseline: 2.1935x; 1.2300x over previous
#include <cuda_runtime.h>
#include <cuda_bf16.h>
#include <cstdint>

#define KDIM 256
#define NIT 50
#define TPITCH 36   // floats per tile row: conflict-free LDS.128/STS via cp.async

__device__ float g_loss[512];
__device__ unsigned g_cnt = 0;

static constexpr int SMEM_MS_OFF    = 0;                          // 256*256 bf16 = 131072
static constexpr int SMEM_TILEA_OFF = 131072;                     // 256*36*4 = 36864
static constexpr int SMEM_TILEB_OFF = SMEM_TILEA_OFF + 36864;     // 167936
static constexpr int SMEM_FSH_OFF   = SMEM_TILEB_OFF + 36864;     // 204800
static constexpr int SMEM_GSH_OFF   = SMEM_FSH_OFF + 1024;        // 205824
static constexpr int SMEM_RED_OFF   = SMEM_GSH_OFF + 1024;        // 206848
static constexpr int SMEM_BYTES     = SMEM_RED_OFF + 256;         // 207104

__device__ __forceinline__ void cp16(uint32_t dst, const float4* src) {
    asm volatile("cp.async.cg.shared.global [%0], [%1], 16;" :: "r"(dst), "l"(src));
}
__device__ __forceinline__ void cp_commit() { asm volatile("cp.async.commit_group;"); }
__device__ __forceinline__ void cp_wait1()  { asm volatile("cp.async.wait_group 1;"); }
__device__ __forceinline__ void cp_wait0()  { asm volatile("cp.async.wait_group 0;"); }

__global__ void __launch_bounds__(256)
cacis_main(const float* __restrict__ scores, const int* __restrict__ targets,
           const float* __restrict__ C, float* __restrict__ out, int B)
{
    extern __shared__ unsigned char smem[];
    __nv_bfloat16* MS  = reinterpret_cast<__nv_bfloat16*>(smem + SMEM_MS_OFF);
    float* tilep[2] = { reinterpret_cast<float*>(smem + SMEM_TILEA_OFF),
                        reinterpret_cast<float*>(smem + SMEM_TILEB_OFF) };
    float* fsh = reinterpret_cast<float*>(smem + SMEM_FSH_OFF);
    float* gsh = reinterpret_cast<float*>(smem + SMEM_GSH_OFF);
    float* red = reinterpret_cast<float*>(smem + SMEM_RED_OFF);
    const float4* fsh4 = reinterpret_cast<const float4*>(fsh);

    const int t    = threadIdx.x;
    const int lane = t & 31;
    const int warp = t >> 5;
    const int b    = blockIdx.x;
    const float*  __restrict__ Cb  = C + (size_t)b * (KDIM * KDIM);
    const float4* __restrict__ Cb4 = reinterpret_cast<const float4*>(Cb);

    uint32_t tbase[2];
    tbase[0] = (uint32_t)__cvta_generic_to_shared(tilep[0]);
    tbase[1] = (uint32_t)__cvta_generic_to_shared(tilep[1]);

    fsh[t] = 0.5f * scores[b * KDIM + t];
    __syncthreads();
    const float f_r = fsh[t];

    // prefetch a 256x32 fp32 tile (cols j0..j0+31) into buffer buf
#define PREFETCH(j0_, buf_) do {                                               \
        _Pragma("unroll")                                                      \
        for (int kk = 0; kk < 8; kk++) {                                       \
            int f4 = kk * 256 + t;                                             \
            int row = f4 >> 3, c4 = f4 & 7;                                    \
            cp16(tbase[buf_] + (uint32_t)((row * TPITCH + c4 * 4) * 4),        \
                 Cb4 + row * 64 + ((j0_) >> 2) + c4);                          \
        }                                                                      \
        cp_commit();                                                           \
    } while (0)

    // ---------------- PASS 1: sum, trace, min(f_i+f_j+C) — pipelined ----------------
    float psum = 0.f, ptrc = 0.f, pmin = 3.402823466e38f;
    PREFETCH(0, 0);
    for (int k = 0; k < 8; k++) {
        if (k < 7) { PREFETCH((k + 1) * 32, (k + 1) & 1); cp_wait1(); }
        else       { cp_wait0(); }
        __syncthreads();
        const float* tl = tilep[k & 1];
        const int j0 = k * 32;
#pragma unroll
        for (int c4 = 0; c4 < 8; c4++) {
            float4 v  = *reinterpret_cast<const float4*>(tl + t * TPITCH + c4 * 4);
            float4 fc = fsh4[(j0 >> 2) + c4];
            psum += (v.x + v.y) + (v.z + v.w);
            pmin = fminf(pmin, f_r + fminf(fminf(fc.x + v.x, fc.y + v.y),
                                           fminf(fc.z + v.z, fc.w + v.w)));
        }
        if ((unsigned)(t - j0) < 32u) ptrc += tl[t * TPITCH + (t - j0)];
        __syncthreads();
    }
    PREFETCH(0, 0);   // head start for pass 2 (tileA long since consumed)
#pragma unroll
    for (int o = 16; o; o >>= 1) {
        psum += __shfl_xor_sync(0xffffffffu, psum, o);
        ptrc += __shfl_xor_sync(0xffffffffu, ptrc, o);
        pmin  = fminf(pmin, __shfl_xor_sync(0xffffffffu, pmin, o));
    }
    if (lane == 0) { red[warp] = psum; red[8 + warp] = ptrc; red[16 + warp] = pmin; }
    __syncthreads();
    if (t == 0) {
        float s = 0.f, tr = 0.f, mn = 3.402823466e38f;
#pragma unroll
        for (int w = 0; w < 8; w++) { s += red[w]; tr += red[8 + w]; mn = fminf(mn, red[16 + w]); }
        float eps = fmaxf((s - tr) * (1.0f / (KDIM * KDIM - KDIM)), 1e-8f);
        red[24] = eps; red[25] = 1.0f / eps; red[26] = mn;
    }
    __syncthreads();
    const float eps = red[24], inv_eps = red[25], minval = red[26];

    // ---------------- PASS 2: M = exp(..) -> bf16 col-major + rowsums — pipelined ----------------
    float rowsum = 0.f;
    for (int k = 0; k < 8; k++) {
        if (k < 7) { PREFETCH((k + 1) * 32, (k + 1) & 1); cp_wait1(); }
        else       { cp_wait0(); }
        __syncthreads();
        const float* tl = tilep[k & 1];
        const int j0 = k * 32;
        const float base = minval - f_r;
#pragma unroll
        for (int c4 = 0; c4 < 8; c4++) {
            float4 v  = *reinterpret_cast<const float4*>(tl + t * TPITCH + c4 * 4);
            float4 fc = fsh4[(j0 >> 2) + c4];
            float m0 = __expf((base - (fc.x + v.x)) * inv_eps);
            float m1 = __expf((base - (fc.y + v.y)) * inv_eps);
            float m2 = __expf((base - (fc.z + v.z)) * inv_eps);
            float m3 = __expf((base - (fc.w + v.w)) * inv_eps);
            int col = j0 + c4 * 4;
            MS[(col + 0) * 256 + t] = __float2bfloat16(m0);
            MS[(col + 1) * 256 + t] = __float2bfloat16(m1);
            MS[(col + 2) * 256 + t] = __float2bfloat16(m2);
            MS[(col + 3) * 256 + t] = __float2bfloat16(m3);
            rowsum += (m0 + m1) + (m2 + m3);
        }
        __syncthreads();
    }
    gsh[t] = rowsum * (2.0f / KDIM);
    __syncthreads();

    // ---------------- Frank-Wolfe in warp 0; other warps wait at the tail barrier ----------------
    int*   sidx = reinterpret_cast<int*>(tilep[0]);
    float* sval = tilep[0] + 64;
    int*   redi = reinterpret_cast<int*>(red);

    if (warp == 0) {
        float g[8], a[8];
#pragma unroll
        for (int kq = 0; kq < 8; kq++) { g[kq] = gsh[lane * 8 + kq]; a[kq] = 1.0f / KDIM; }

        for (int it = 0; it < NIT; it++) {
            unsigned c0 = (__float_as_uint(g[0]) & 0xFFFFFF00u) | (unsigned)(lane * 8 + 0);
            unsigned c1 = (__float_as_uint(g[1]) & 0xFFFFFF00u) | (unsigned)(lane * 8 + 1);
            unsigned c2 = (__float_as_uint(g[2]) & 0xFFFFFF00u) | (unsigned)(lane * 8 + 2);
            unsigned c3 = (__float_as_uint(g[3]) & 0xFFFFFF00u) | (unsigned)(lane * 8 + 3);
            unsigned c4k = (__float_as_uint(g[4]) & 0xFFFFFF00u) | (unsigned)(lane * 8 + 4);
            unsigned c5 = (__float_as_uint(g[5]) & 0xFFFFFF00u) | (unsigned)(lane * 8 + 5);
            unsigned c6 = (__float_as_uint(g[6]) & 0xFFFFFF00u) | (unsigned)(lane * 8 + 6);
            unsigned c7 = (__float_as_uint(g[7]) & 0xFFFFFF00u) | (unsigned)(lane * 8 + 7);
            unsigned key = min(min(min(c0, c1), min(c2, c3)), min(min(c4k, c5), min(c6, c7)));
            key = __reduce_min_sync(0xffffffffu, key);
            int istar = (int)(key & 0xFFu);

            float gamma = 2.0f / ((float)it + 2.0f);
            float om = 1.0f - gamma;
            float tg = 2.0f * gamma;

            uint4 q = *reinterpret_cast<const uint4*>(MS + (istar << 8) + lane * 8);
            __nv_bfloat162* h2 = reinterpret_cast<__nv_bfloat162*>(&q);
            float mcol[8];
#pragma unroll
            for (int p = 0; p < 4; p++) {
                float2 f2 = __bfloat1622float2(h2[p]);
                mcol[2 * p] = f2.x; mcol[2 * p + 1] = f2.y;
            }
#pragma unroll
            for (int kq = 0; kq < 8; kq++) {
                a[kq] = om * a[kq] + (((lane * 8 + kq) == istar) ? gamma : 0.f);
                g[kq] = fmaf(tg, mcol[kq], om * g[kq]);
            }
        }

        // compact support into smem
        int nS = 0;
#pragma unroll
        for (int kq = 0; kq < 8; kq++) {
            bool nz = (a[kq] > 0.f);
            unsigned m = __ballot_sync(0xffffffffu, nz);
            if (nz) {
                int pos = nS + __popc(m & ((1u << lane) - 1u));
                sidx[pos] = lane * 8 + kq;
                sval[pos] = a[kq];
            }
            nS += __popc(m);
        }
        if (lane == 0) redi[27] = nS;
    }
    __syncthreads();

    // ---------------- exact val = alpha^T M alpha — all 256 threads ----------------
    {
        const int nS  = redi[27];
        const int tot = nS * nS;
        float vp = 0.f;
        for (int p = t; p < tot; p += 256) {
            int pi = p / nS, pj = p - pi * nS;
            int i = sidx[pi], j = sidx[pj];
            float e = (minval - fsh[i] - fsh[j] - Cb[(i << 8) + j]) * inv_eps;
            vp += sval[pi] * sval[pj] * __expf(e);
        }
#pragma unroll
        for (int o = 16; o; o >>= 1) vp += __shfl_xor_sync(0xffffffffu, vp, o);
        if (lane == 0) red[32 + warp] = vp;
    }
    __syncthreads();
    if (warp != 0) return;

    // ---------------- per-batch loss + fused last-CTA mean reduction (warp 0) ----------------
    float vtot = (lane < 8) ? red[32 + lane] : 0.f;
#pragma unroll
    for (int o = 4; o; o >>= 1) vtot += __shfl_xor_sync(0xffffffffu, vtot, o);
    vtot = __shfl_sync(0xffffffffu, vtot, 0);

    unsigned prev = 0;
    if (lane == 0) {
        g_loss[b] = minval - eps * logf(vtot) - scores[b * KDIM + targets[b]];
        __threadfence();
        prev = atomicAdd(&g_cnt, 1u);
    }
    prev = __shfl_sync(0xffffffffu, prev, 0);
    if ((int)prev == B - 1) {
        __threadfence();
        float s = 0.f;
        volatile float* gl = g_loss;
        for (int i = lane; i < B; i += 32) s += gl[i];
#pragma unroll
        for (int o = 16; o; o >>= 1) s += __shfl_xor_sync(0xffffffffu, s, o);
        if (lane == 0) { out[0] = s / (float)B; g_cnt = 0; }
    }
}

extern "C" void kernel_launch(void* const* d_in, const int* in_sizes, int n_in,
                              void* d_out, int out_size)
{
    int imin = 0, imax = 0;
    for (int i = 1; i < n_in; i++) {
        if (in_sizes[i] < in_sizes[imin]) imin = i;
        if (in_sizes[i] > in_sizes[imax]) imax = i;
    }
    int imid = 3 - imin - imax;
    const float* scores  = (const float*)d_in[imid];
    const int*   targets = (const int*)d_in[imin];
    const float* C       = (const float*)d_in[imax];
    int B = in_sizes[imin];

    cudaFuncSetAttribute(cacis_main, cudaFuncAttributeMaxDynamicSharedMemorySize, SMEM_BYTES);
    cacis_main<<<B, 256, SMEM_BYTES>>>(scores, targets, C, (float*)d_out, B);
}

// round 5
// speedup vs baseline: 3.0449x; 1.3882x over previous
#include <cuda_runtime.h>
#include <cstdint>

#define KDIM 256
#define NIT 50
#define TCOLS 16
#define TPITCH 20      // floats per staged-tile row (80B, cp.async 16B-aligned)
#define C8PITCH 260    // bytes per C8 column (65 words -> bank-friendly)
#define NTILE 16

__device__ float g_loss[512];
__device__ unsigned g_cnt = 0;

static constexpr int SMEM_C8_OFF    = 0;          // 256*260      = 66560
static constexpr int SMEM_TILEA_OFF = 66560;      // 256*20*4     = 20480
static constexpr int SMEM_TILEB_OFF = 87040;      // 20480
static constexpr int SMEM_FSH_OFF   = 107520;     // 1024
static constexpr int SMEM_ECOL_OFF  = 108544;     // 1024
static constexpr int SMEM_LUT_OFF   = 109568;     // 1024
static constexpr int SMEM_GSH_OFF   = 110592;     // 1024
static constexpr int SMEM_RED_OFF   = 111616;     // 256
static constexpr int SMEM_BYTES     = 111872;     // 109.25 KB -> 2 CTAs/SM

__device__ __forceinline__ void cp16(uint32_t dst, const float4* src) {
    asm volatile("cp.async.cg.shared.global [%0], [%1], 16;" :: "r"(dst), "l"(src));
}
__device__ __forceinline__ void cp_commit() { asm volatile("cp.async.commit_group;"); }
__device__ __forceinline__ void cp_wait1()  { asm volatile("cp.async.wait_group 1;"); }
__device__ __forceinline__ void cp_wait0()  { asm volatile("cp.async.wait_group 0;"); }

__global__ void __launch_bounds__(256, 2)
cacis_main(const float* __restrict__ scores, const int* __restrict__ targets,
           const float* __restrict__ C, float* __restrict__ out, int B)
{
    extern __shared__ unsigned char smem[];
    unsigned char* c8 = smem + SMEM_C8_OFF;
    float* tilep[2] = { reinterpret_cast<float*>(smem + SMEM_TILEA_OFF),
                        reinterpret_cast<float*>(smem + SMEM_TILEB_OFF) };
    float* fsh  = reinterpret_cast<float*>(smem + SMEM_FSH_OFF);
    float* ecol = reinterpret_cast<float*>(smem + SMEM_ECOL_OFF);
    float* lut  = reinterpret_cast<float*>(smem + SMEM_LUT_OFF);
    float* gsh  = reinterpret_cast<float*>(smem + SMEM_GSH_OFF);
    float* red  = reinterpret_cast<float*>(smem + SMEM_RED_OFF);
    float* gp   = tilep[0];                          // overlay (dead after pass 1)
    int*   sidx = reinterpret_cast<int*>(tilep[1]);  // overlay
    float* sval = tilep[1] + 64;
    int*   redi = reinterpret_cast<int*>(red);

    const int t    = threadIdx.x;
    const int lane = t & 31;
    const int warp = t >> 5;
    const int b    = blockIdx.x;
    const float*  __restrict__ Cb  = C + (size_t)b * (KDIM * KDIM);
    const float4* __restrict__ Cb4 = reinterpret_cast<const float4*>(Cb);

    uint32_t tbase[2];
    tbase[0] = (uint32_t)__cvta_generic_to_shared(tilep[0]);
    tbase[1] = (uint32_t)__cvta_generic_to_shared(tilep[1]);

    fsh[t] = 0.5f * scores[b * KDIM + t];
    __syncthreads();

    // stage a 256x16 fp32 tile (cols j0..j0+15)
#define PREFETCH(j0_, buf_) do {                                               \
        _Pragma("unroll")                                                      \
        for (int kk = 0; kk < 4; kk++) {                                       \
            int id = kk * 256 + t;                                             \
            int row = id >> 2, c4 = id & 3;                                    \
            cp16(tbase[buf_] + (uint32_t)((row * TPITCH + c4 * 4) * 4),        \
                 Cb4 + row * 64 + ((j0_) >> 2) + c4);                          \
        }                                                                      \
        cp_commit();                                                           \
    } while (0)

    // ---------- PASS 1: sum/trace/min + quantize C -> u8 col-major smem ----------
    float psum = 0.f, ptrc = 0.f, pmin = 3.402823466e38f;
    const int lc   = t & 15;
    const int sgrp = t >> 4;
    PREFETCH(0, 0);
    for (int k = 0; k < NTILE; k++) {
        if (k < NTILE - 1) { PREFETCH((k + 1) * TCOLS, (k + 1) & 1); cp_wait1(); }
        else               { cp_wait0(); }
        __syncthreads();
        const float* tl = tilep[k & 1];
        const int col = k * TCOLS + lc;
        const float fc = fsh[col];
        unsigned char* c8col = c8 + col * C8PITCH;
#pragma unroll
        for (int s = 0; s < 4; s++) {
            int row0 = s * 64 + sgrp * 4;
            float v0 = tl[(row0 + 0) * TPITCH + lc];
            float v1 = tl[(row0 + 1) * TPITCH + lc];
            float v2 = tl[(row0 + 2) * TPITCH + lc];
            float v3 = tl[(row0 + 3) * TPITCH + lc];
            psum += (v0 + v1) + (v2 + v3);
            float e0 = fsh[row0 + 0] + v0, e1 = fsh[row0 + 1] + v1;
            float e2 = fsh[row0 + 2] + v2, e3 = fsh[row0 + 3] + v3;
            pmin = fminf(pmin, fc + fminf(fminf(e0, e1), fminf(e2, e3)));
            if (col == row0 + 0) ptrc += v0;
            if (col == row0 + 1) ptrc += v1;
            if (col == row0 + 2) ptrc += v2;
            if (col == row0 + 3) ptrc += v3;
            uint32_t q0 = __float2uint_rn(v0 * 255.f);
            uint32_t q1 = __float2uint_rn(v1 * 255.f);
            uint32_t q2 = __float2uint_rn(v2 * 255.f);
            uint32_t q3 = __float2uint_rn(v3 * 255.f);
            *reinterpret_cast<uint32_t*>(c8col + row0) =
                q0 | (q1 << 8) | (q2 << 16) | (q3 << 24);
        }
        __syncthreads();
    }
#pragma unroll
    for (int o = 16; o; o >>= 1) {
        psum += __shfl_xor_sync(0xffffffffu, psum, o);
        ptrc += __shfl_xor_sync(0xffffffffu, ptrc, o);
        pmin  = fminf(pmin, __shfl_xor_sync(0xffffffffu, pmin, o));
    }
    if (lane == 0) { red[warp] = psum; red[8 + warp] = ptrc; red[16 + warp] = pmin; }
    __syncthreads();
    if (t == 0) {
        float s = 0.f, tr = 0.f, mn = 3.402823466e38f;
#pragma unroll
        for (int w = 0; w < 8; w++) { s += red[w]; tr += red[8 + w]; mn = fminf(mn, red[16 + w]); }
        float eps = fmaxf((s - tr) * (1.0f / (KDIM * KDIM - KDIM)), 1e-8f);
        red[24] = eps; red[25] = 1.0f / eps; red[26] = mn;
    }
    __syncthreads();
    const float eps = red[24], inv_eps = red[25], minval = red[26];
    const float inv255eps = inv_eps * (1.0f / 255.0f);

    // exp tables:  M~_ij = ecol[i]*ecol[j]*lut[q_ij]   (global exp(minval/eps) factor dropped:
    // it scales all grads uniformly -> argmin & alpha invariant; exact value recomputed later)
    ecol[t] = __expf(-fsh[t] * inv_eps);
    lut[t]  = __expf(-(float)t * inv255eps);
    __syncthreads();

    // ---------- PASS 2: rowsums of M~ from c8 (no gmem, no MUFU) ----------
    {
        const int cg = t >> 6;
        const int r0 = (t & 63) * 4;
        float s0 = 0.f, s1 = 0.f, s2 = 0.f, s3 = 0.f;
#pragma unroll 8
        for (int cc = 0; cc < 64; cc++) {
            int col = cg * 64 + cc;
            uint32_t p = *reinterpret_cast<const uint32_t*>(c8 + col * C8PITCH + r0);
            float ec = ecol[col];
            s0 = fmaf(ec, lut[p & 255u],         s0);
            s1 = fmaf(ec, lut[(p >> 8)  & 255u], s1);
            s2 = fmaf(ec, lut[(p >> 16) & 255u], s2);
            s3 = fmaf(ec, lut[p >> 24],          s3);
        }
        gp[cg * 256 + r0 + 0] = s0 * ecol[r0 + 0];
        gp[cg * 256 + r0 + 1] = s1 * ecol[r0 + 1];
        gp[cg * 256 + r0 + 2] = s2 * ecol[r0 + 2];
        gp[cg * 256 + r0 + 3] = s3 * ecol[r0 + 3];
    }
    __syncthreads();
    gsh[t] = (gp[t] + gp[256 + t] + gp[512 + t] + gp[768 + t]) * (2.0f / KDIM);
    __syncthreads();

    // ---------- Frank-Wolfe (warp 0), columns rebuilt from c8 via lut ----------
    if (warp == 0) {
        float g[8], a[8], eci[8];
#pragma unroll
        for (int kq = 0; kq < 8; kq++) {
            g[kq] = gsh[lane * 8 + kq];
            a[kq] = 1.0f / KDIM;
            eci[kq] = ecol[lane * 8 + kq];
        }
        for (int it = 0; it < NIT; it++) {
            unsigned c0 = (__float_as_uint(g[0]) & 0xFFFFFF00u) | (unsigned)(lane * 8 + 0);
            unsigned c1 = (__float_as_uint(g[1]) & 0xFFFFFF00u) | (unsigned)(lane * 8 + 1);
            unsigned c2 = (__float_as_uint(g[2]) & 0xFFFFFF00u) | (unsigned)(lane * 8 + 2);
            unsigned c3 = (__float_as_uint(g[3]) & 0xFFFFFF00u) | (unsigned)(lane * 8 + 3);
            unsigned c4 = (__float_as_uint(g[4]) & 0xFFFFFF00u) | (unsigned)(lane * 8 + 4);
            unsigned c5 = (__float_as_uint(g[5]) & 0xFFFFFF00u) | (unsigned)(lane * 8 + 5);
            unsigned c6 = (__float_as_uint(g[6]) & 0xFFFFFF00u) | (unsigned)(lane * 8 + 6);
            unsigned c7 = (__float_as_uint(g[7]) & 0xFFFFFF00u) | (unsigned)(lane * 8 + 7);
            unsigned key = min(min(min(c0, c1), min(c2, c3)), min(min(c4, c5), min(c6, c7)));
            key = __reduce_min_sync(0xffffffffu, key);
            int istar = (int)(key & 0xFFu);

            float gamma = 2.0f / ((float)it + 2.0f);
            float om = 1.0f - gamma;
            float tge = 2.0f * gamma * ecol[istar];

            const unsigned char* cc8 = c8 + istar * C8PITCH + lane * 8;
            uint32_t p0 = *reinterpret_cast<const uint32_t*>(cc8);
            uint32_t p1 = *reinterpret_cast<const uint32_t*>(cc8 + 4);

            g[0] = fmaf(tge * eci[0], lut[p0 & 255u],         om * g[0]);
            g[1] = fmaf(tge * eci[1], lut[(p0 >> 8)  & 255u], om * g[1]);
            g[2] = fmaf(tge * eci[2], lut[(p0 >> 16) & 255u], om * g[2]);
            g[3] = fmaf(tge * eci[3], lut[p0 >> 24],          om * g[3]);
            g[4] = fmaf(tge * eci[4], lut[p1 & 255u],         om * g[4]);
            g[5] = fmaf(tge * eci[5], lut[(p1 >> 8)  & 255u], om * g[5]);
            g[6] = fmaf(tge * eci[6], lut[(p1 >> 16) & 255u], om * g[6]);
            g[7] = fmaf(tge * eci[7], lut[p1 >> 24],          om * g[7]);
#pragma unroll
            for (int kq = 0; kq < 8; kq++)
                a[kq] = om * a[kq] + (((lane * 8 + kq) == istar) ? gamma : 0.f);
        }
        // compact support
        int nS = 0;
#pragma unroll
        for (int kq = 0; kq < 8; kq++) {
            bool nz = (a[kq] > 0.f);
            unsigned m = __ballot_sync(0xffffffffu, nz);
            if (nz) {
                int pos = nS + __popc(m & ((1u << lane) - 1u));
                sidx[pos] = lane * 8 + kq;
                sval[pos] = a[kq];
            }
            nS += __popc(m);
        }
        if (lane == 0) redi[27] = nS;
    }
    __syncthreads();

    // ---------- exact val = alpha^T M alpha (gmem C, full precision), 256 threads ----------
    {
        const int nS  = redi[27];
        const int tot = nS * nS;
        float vp = 0.f;
        for (int p = t; p < tot; p += 256) {
            int pi = p / nS, pj = p - pi * nS;
            int i = sidx[pi], j = sidx[pj];
            float e = (minval - fsh[i] - fsh[j] - Cb[(i << 8) + j]) * inv_eps;
            vp += sval[pi] * sval[pj] * __expf(e);
        }
#pragma unroll
        for (int o = 16; o; o >>= 1) vp += __shfl_xor_sync(0xffffffffu, vp, o);
        if (lane == 0) red[32 + warp] = vp;
    }
    __syncthreads();
    if (warp != 0) return;

    float vtot = (lane < 8) ? red[32 + lane] : 0.f;
#pragma unroll
    for (int o = 4; o; o >>= 1) vtot += __shfl_xor_sync(0xffffffffu, vtot, o);
    vtot = __shfl_sync(0xffffffffu, vtot, 0);

    unsigned prev = 0;
    if (lane == 0) {
        g_loss[b] = minval - eps * logf(vtot) - scores[b * KDIM + targets[b]];
        __threadfence();
        prev = atomicAdd(&g_cnt, 1u);
    }
    prev = __shfl_sync(0xffffffffu, prev, 0);
    if ((int)prev == B - 1) {
        __threadfence();
        float s = 0.f;
        volatile float* gl = g_loss;
        for (int i = lane; i < B; i += 32) s += gl[i];
#pragma unroll
        for (int o = 16; o; o >>= 1) s += __shfl_xor_sync(0xffffffffu, s, o);
        if (lane == 0) { out[0] = s / (float)B; g_cnt = 0; }
    }
}

extern "C" void kernel_launch(void* const* d_in, const int* in_sizes, int n_in,
                              void* d_out, int out_size)
{
    int imin = 0, imax = 0;
    for (int i = 1; i < n_in; i++) {
        if (in_sizes[i] < in_sizes[imin]) imin = i;
        if (in_sizes[i] > in_sizes[imax]) imax = i;
    }
    int imid = 3 - imin - imax;
    const float* scores  = (const float*)d_in[imid];
    const int*   targets = (const int*)d_in[imin];
    const float* C       = (const float*)d_in[imax];
    int B = in_sizes[imin];

    cudaFuncSetAttribute(cacis_main, cudaFuncAttributeMaxDynamicSharedMemorySize, SMEM_BYTES);
    cacis_main<<<B, 256, SMEM_BYTES>>>(scores, targets, C, (float*)d_out, B);
}